// round 14
// baseline (speedup 1.0000x reference)
#include <cuda_runtime.h>
#include <cuda_bf16.h>
#include <cstdint>

// out[b,o,p] = sum_c refine_w[o,c]*x[b,c,p] + refine_b[o]
// (rest of reference graph is dead: x_back == x exactly, _dead unused)
// B=8, C=64, HW=65536, fp32.
//
// R13/R14: warp-level mma.sync bf16 (HMMA on sm_103; tcgen05 rejected by the
// harness's non-'a' target). Split precision: x=xh+xl, w=wh+wl;
// D = AhBh + AhBl + AlBh accumulated in fp32 (~1e-5 rel err).
// Per warp: 16 pixels x 64 outputs, K=64 -> 8 n-tiles x 4 k-steps x 3 = 96 mma.

#define CC   64
#define HW   65536
#define BP   128          // pixels per CTA (8 warps x 16)
#define NTHR 256

static __device__ __forceinline__ void bf16_split2(float a, float b,
                                                   uint32_t& hi, uint32_t& lo)
{
    __nv_bfloat16 ha = __float2bfloat16_rn(a);
    __nv_bfloat16 hb = __float2bfloat16_rn(b);
    float ra = a - __bfloat162float(ha);
    float rb = b - __bfloat162float(hb);
    __nv_bfloat162 H; H.x = ha; H.y = hb;                 // low half = first elem
    __nv_bfloat162 L = __floats2bfloat162_rn(ra, rb);
    hi = *reinterpret_cast<uint32_t*>(&H);
    lo = *reinterpret_cast<uint32_t*>(&L);
}

static __device__ __forceinline__ void mma16816(float* d, const uint32_t* a,
                                                uint32_t b0, uint32_t b1)
{
    asm volatile(
        "mma.sync.aligned.m16n8k16.row.col.f32.bf16.bf16.f32 "
        "{%0,%1,%2,%3}, {%4,%5,%6,%7}, {%8,%9}, {%0,%1,%2,%3};"
        : "+f"(d[0]), "+f"(d[1]), "+f"(d[2]), "+f"(d[3])
        : "r"(a[0]), "r"(a[1]), "r"(a[2]), "r"(a[3]), "r"(b0), "r"(b1));
}

__global__ __launch_bounds__(NTHR) void conv1x1_mma_kernel(
    const float* __restrict__ x,
    const float* __restrict__ w,      // [64][64] (o,c)
    const float* __restrict__ bias,   // [64]
    float* __restrict__ out)
{
    // weights as bf16x2 (c, c+1) pairs: [o][32 pairs], hi and lo splits (16 KB)
    __shared__ uint32_t sh_bh[CC * 32];
    __shared__ uint32_t sh_bl[CC * 32];

    const int t    = threadIdx.x;
    const int wid  = t >> 5;
    const int lane = t & 31;
    const int gid  = lane >> 2;     // group id: pixel row / B col
    const int tig  = lane & 3;      // thread in group: k / out col pairs
    const int b    = blockIdx.y;
    const int p0   = blockIdx.x * BP + wid * 16;   // this warp's 16 pixels

    // ---- build weight smem: 2048 bf16x2 pairs, 8 per thread ----
#pragma unroll
    for (int k = 0; k < 8; k++) {
        int i  = t + k * NTHR;      // pair index = o*32 + cp
        int o  = i >> 5;
        int cp = i & 31;
        float v0 = __ldg(w + o * CC + 2 * cp);
        float v1 = __ldg(w + o * CC + 2 * cp + 1);
        uint32_t hi, lo;
        bf16_split2(v0, v1, hi, lo);
        sh_bh[i] = hi;
        sh_bl[i] = lo;
    }
    __syncthreads();

    float d[8][4];
#pragma unroll
    for (int nt = 0; nt < 8; nt++)
#pragma unroll
        for (int q = 0; q < 4; q++) d[nt][q] = 0.f;

    const float* xg = x + (size_t)b * CC * HW + p0;

#pragma unroll
    for (int ks = 0; ks < 4; ks++) {
        // A fragment channels: ca=ks*16+2*tig (regs a0/a1), cb=ca+8 (a2/a3)
        const int ca = ks * 16 + 2 * tig;
        const int cb = ca + 8;
        // 8 gmem floats (4 channels x 2 pixel rows), sector-coalesced
        float v0 = __ldg(xg + (size_t)ca       * HW + gid);
        float v1 = __ldg(xg + (size_t)(ca + 1) * HW + gid);
        float v2 = __ldg(xg + (size_t)ca       * HW + gid + 8);
        float v3 = __ldg(xg + (size_t)(ca + 1) * HW + gid + 8);
        float v4 = __ldg(xg + (size_t)cb       * HW + gid);
        float v5 = __ldg(xg + (size_t)(cb + 1) * HW + gid);
        float v6 = __ldg(xg + (size_t)cb       * HW + gid + 8);
        float v7 = __ldg(xg + (size_t)(cb + 1) * HW + gid + 8);

        uint32_t ah[4], al[4];
        bf16_split2(v0, v1, ah[0], al[0]);   // (row gid,   k=ca,ca+1)
        bf16_split2(v2, v3, ah[1], al[1]);   // (row gid+8, k=ca,ca+1)
        bf16_split2(v4, v5, ah[2], al[2]);   // (row gid,   k=cb,cb+1)
        bf16_split2(v6, v7, ah[3], al[3]);   // (row gid+8, k=cb,cb+1)

        const int cp0 = ks * 8 + tig;        // b0 pair index (k=2tig,2tig+1)
        const int cp1 = cp0 + 4;             // b1 pair index (k=8+2tig,+1)

#pragma unroll
        for (int nt = 0; nt < 8; nt++) {
            const int o = nt * 8 + gid;      // B fragment column
            uint32_t bh0 = sh_bh[o * 32 + cp0];
            uint32_t bh1 = sh_bh[o * 32 + cp1];
            uint32_t bl0 = sh_bl[o * 32 + cp0];
            uint32_t bl1 = sh_bl[o * 32 + cp1];
            mma16816(d[nt], ah, bh0, bh1);   // hh
            mma16816(d[nt], ah, bl0, bl1);   // h * lo(w)
            mma16816(d[nt], al, bh0, bh1);   // lo(x) * h
        }
    }

    // ---- epilogue: + bias, sector-coalesced STG.32 ----
    float* og = out + (size_t)b * CC * HW + p0;
#pragma unroll
    for (int nt = 0; nt < 8; nt++) {
        const int o0 = nt * 8 + 2 * tig;
        float bo0 = __ldg(bias + o0);
        float bo1 = __ldg(bias + o0 + 1);
        og[(size_t)o0       * HW + gid]     = d[nt][0] + bo0;
        og[(size_t)(o0 + 1) * HW + gid]     = d[nt][1] + bo1;
        og[(size_t)o0       * HW + gid + 8] = d[nt][2] + bo0;
        og[(size_t)(o0 + 1) * HW + gid + 8] = d[nt][3] + bo1;
    }
}

extern "C" void kernel_launch(void* const* d_in, const int* in_sizes, int n_in,
                              void* d_out, int out_size)
{
    (void)in_sizes; (void)n_in; (void)out_size;
    const float* x    = (const float*)d_in[0];   // x
    const float* w    = (const float*)d_in[11];  // refine_w
    const float* bias = (const float*)d_in[12];  // refine_b
    float* out = (float*)d_out;

    dim3 grid(HW / BP, 8);   // 512 pixel tiles x 8 batches
    conv1x1_mma_kernel<<<grid, NTHR>>>(x, w, bias, out);
}

// round 15
// speedup vs baseline: 2.1848x; 2.1848x over previous
#include <cuda_runtime.h>
#include <cuda_bf16.h>
#include <cstdint>

// out[b,o,p] = sum_c refine_w[o,c]*x[b,c,p] + refine_b[o]
// (rest of reference graph is dead: x_back == x exactly, _dead unused)
// B=8, C=64, HW=65536, fp32.
//
// R15: mma.sync bf16 split-precision (validated rel_err 4e-6 in R14).
// Fix R14's 8-way smem bank conflicts on B-fragment loads with an XOR
// swizzle: addr = o*32 + (cp ^ ((o&7)<<2)). On read o&7==gid, so banks =
// (ks*8+tig) ^ (gid<<2) -> 32 distinct banks, conflict-free.

#define CC   64
#define HW   65536
#define BP   128          // pixels per CTA (8 warps x 16)
#define NTHR 256

#define BSWZ(o, cp) ((o) * 32 + ((cp) ^ (((o) & 7) << 2)))

static __device__ __forceinline__ void bf16_split2(float a, float b,
                                                   uint32_t& hi, uint32_t& lo)
{
    __nv_bfloat16 ha = __float2bfloat16_rn(a);
    __nv_bfloat16 hb = __float2bfloat16_rn(b);
    float ra = a - __bfloat162float(ha);
    float rb = b - __bfloat162float(hb);
    __nv_bfloat162 H; H.x = ha; H.y = hb;                 // low half = first elem
    __nv_bfloat162 L = __floats2bfloat162_rn(ra, rb);
    hi = *reinterpret_cast<uint32_t*>(&H);
    lo = *reinterpret_cast<uint32_t*>(&L);
}

static __device__ __forceinline__ void mma16816(float* d, const uint32_t* a,
                                                uint32_t b0, uint32_t b1)
{
    asm volatile(
        "mma.sync.aligned.m16n8k16.row.col.f32.bf16.bf16.f32 "
        "{%0,%1,%2,%3}, {%4,%5,%6,%7}, {%8,%9}, {%0,%1,%2,%3};"
        : "+f"(d[0]), "+f"(d[1]), "+f"(d[2]), "+f"(d[3])
        : "r"(a[0]), "r"(a[1]), "r"(a[2]), "r"(a[3]), "r"(b0), "r"(b1));
}

__global__ __launch_bounds__(NTHR) void conv1x1_mma_kernel(
    const float* __restrict__ x,
    const float* __restrict__ w,      // [64][64] (o,c)
    const float* __restrict__ bias,   // [64]
    float* __restrict__ out)
{
    // weights as bf16x2 (c, c+1) pairs: [o][32 pairs] XOR-swizzled, hi+lo (16 KB)
    __shared__ uint32_t sh_bh[CC * 32];
    __shared__ uint32_t sh_bl[CC * 32];

    const int t    = threadIdx.x;
    const int wid  = t >> 5;
    const int lane = t & 31;
    const int gid  = lane >> 2;     // group id: pixel row / B col
    const int tig  = lane & 3;      // thread in group: k / out col pairs
    const int b    = blockIdx.y;
    const int p0   = blockIdx.x * BP + wid * 16;   // this warp's 16 pixels

    // ---- build weight smem: 2048 bf16x2 pairs, 8 per thread, swizzled ----
#pragma unroll
    for (int k = 0; k < 8; k++) {
        int i  = t + k * NTHR;      // logical pair index = o*32 + cp
        int o  = i >> 5;
        int cp = i & 31;
        float v0 = __ldg(w + o * CC + 2 * cp);
        float v1 = __ldg(w + o * CC + 2 * cp + 1);
        uint32_t hi, lo;
        bf16_split2(v0, v1, hi, lo);
        int si = BSWZ(o, cp);
        sh_bh[si] = hi;
        sh_bl[si] = lo;
    }
    __syncthreads();

    float d[8][4];
#pragma unroll
    for (int nt = 0; nt < 8; nt++)
#pragma unroll
        for (int q = 0; q < 4; q++) d[nt][q] = 0.f;

    const float* xg = x + (size_t)b * CC * HW + p0;

#pragma unroll
    for (int ks = 0; ks < 4; ks++) {
        // A fragment channels: ca=ks*16+2*tig (regs a0/a1), cb=ca+8 (a2/a3)
        const int ca = ks * 16 + 2 * tig;
        const int cb = ca + 8;
        // 8 gmem floats (4 channels x 2 pixel rows), sector-coalesced
        float v0 = __ldg(xg + (size_t)ca       * HW + gid);
        float v1 = __ldg(xg + (size_t)(ca + 1) * HW + gid);
        float v2 = __ldg(xg + (size_t)ca       * HW + gid + 8);
        float v3 = __ldg(xg + (size_t)(ca + 1) * HW + gid + 8);
        float v4 = __ldg(xg + (size_t)cb       * HW + gid);
        float v5 = __ldg(xg + (size_t)(cb + 1) * HW + gid);
        float v6 = __ldg(xg + (size_t)cb       * HW + gid + 8);
        float v7 = __ldg(xg + (size_t)(cb + 1) * HW + gid + 8);

        uint32_t ah[4], al[4];
        bf16_split2(v0, v1, ah[0], al[0]);   // (row gid,   k=ca,ca+1)
        bf16_split2(v2, v3, ah[1], al[1]);   // (row gid+8, k=ca,ca+1)
        bf16_split2(v4, v5, ah[2], al[2]);   // (row gid,   k=cb,cb+1)
        bf16_split2(v6, v7, ah[3], al[3]);   // (row gid+8, k=cb,cb+1)

        const int cp0 = ks * 8 + tig;        // b0 pair index (k=2tig,2tig+1)
        const int cp1 = cp0 + 4;             // b1 pair index (k=8+2tig,+1)

#pragma unroll
        for (int nt = 0; nt < 8; nt++) {
            const int o = nt * 8 + gid;      // B fragment column
            uint32_t bh0 = sh_bh[BSWZ(o, cp0)];
            uint32_t bh1 = sh_bh[BSWZ(o, cp1)];
            uint32_t bl0 = sh_bl[BSWZ(o, cp0)];
            uint32_t bl1 = sh_bl[BSWZ(o, cp1)];
            mma16816(d[nt], ah, bh0, bh1);   // hh
            mma16816(d[nt], ah, bl0, bl1);   // h * lo(w)
            mma16816(d[nt], al, bh0, bh1);   // lo(x) * h
        }
    }

    // ---- epilogue: + bias, sector-coalesced STG.32 ----
    float* og = out + (size_t)b * CC * HW + p0;
#pragma unroll
    for (int nt = 0; nt < 8; nt++) {
        const int o0 = nt * 8 + 2 * tig;
        float bo0 = __ldg(bias + o0);
        float bo1 = __ldg(bias + o0 + 1);
        og[(size_t)o0       * HW + gid]     = d[nt][0] + bo0;
        og[(size_t)(o0 + 1) * HW + gid]     = d[nt][1] + bo1;
        og[(size_t)o0       * HW + gid + 8] = d[nt][2] + bo0;
        og[(size_t)(o0 + 1) * HW + gid + 8] = d[nt][3] + bo1;
    }
}

extern "C" void kernel_launch(void* const* d_in, const int* in_sizes, int n_in,
                              void* d_out, int out_size)
{
    (void)in_sizes; (void)n_in; (void)out_size;
    const float* x    = (const float*)d_in[0];   // x
    const float* w    = (const float*)d_in[11];  // refine_w
    const float* bias = (const float*)d_in[12];  // refine_b
    float* out = (float*)d_out;

    dim3 grid(HW / BP, 8);   // 512 pixel tiles x 8 batches
    conv1x1_mma_kernel<<<grid, NTHR>>>(x, w, bias, out);
}